// round 15
// baseline (speedup 1.0000x reference)
#include <cuda_runtime.h>
#include <cstdint>
#include <math.h>

// FAVOR+ attention  B=4,N=4096,D=1024,H=16,dk=64,M=256
// R15 = R14 with ZERO new device globals: weight tf32-fragment arrays are
// aliased into g_Spart (lifetimes disjoint: wfq [pre-phik] -> Spart
// [phik..sreduce] -> wfo [post-sreduce]). GEMM byte-identical to R14.
// Controlled A/B vs R13/R14's mem-guard trip (+33.5MB globals suspected).

namespace {
constexpr int B_  = 4;
constexpr int N_  = 4096;
constexpr int D_  = 1024;
constexpr int H_  = 16;
constexpr int DK_ = 64;
constexpr int M_  = 256;
constexpr int BH_ = B_ * H_;
constexpr int CH_ = 16;
}

// -------- device scratch --------
__device__ float g_valid[B_ * N_];
__device__ float g_Q[BH_ * N_ * DK_];
__device__ float g_K[BH_ * N_ * DK_];
__device__ float g_V[BH_ * N_ * DK_];
// Spart doubles as the weight-fragment arena (disjoint lifetimes).
__device__ __align__(16) float g_Spart[(size_t)BH_ * CH_ * M_ * DK_];  // 67MB
__device__ float g_Kpart[BH_ * CH_ * M_];
__device__ float g_S[BH_ * M_ * DK_];
__device__ float g_Ksum[BH_ * M_];
__device__ float g_ctx[(size_t)B_ * N_ * D_];
// omega pre-split, fragment layout: [h][ks(8)][m(256)][tg(4)] uint4
__device__ uint4 g_omf[H_ * 8 * M_ * 4];

// ---- helpers ----
__device__ __forceinline__ uint32_t smem_u32(const void* p) {
    uint32_t a;
    asm("{ .reg .u64 t; cvta.to.shared.u64 t, %1; cvt.u32.u64 %0, t; }"
        : "=r"(a) : "l"(p));
    return a;
}
__device__ __forceinline__ void cp_async16(void* sdst, const void* gsrc) {
    asm volatile("cp.async.cg.shared.global [%0], [%1], 16;"
                 :: "r"(smem_u32(sdst)), "l"(gsrc) : "memory");
}
__device__ __forceinline__ void tf32_split(float f, uint32_t& h, uint32_t& l) {
    uint32_t hb;
    asm("cvt.rna.tf32.f32 %0, %1;" : "=r"(hb) : "f"(f));
    float lf = f - __uint_as_float(hb);
    uint32_t lb;
    asm("cvt.rna.tf32.f32 %0, %1;" : "=r"(lb) : "f"(lf));
    h = hb; l = lb;
}
__device__ __forceinline__ float tf32r(float f) {
    uint32_t hb;
    asm("cvt.rna.tf32.f32 %0, %1;" : "=r"(hb) : "f"(f));
    return __uint_as_float(hb);
}
__device__ __forceinline__ float fexp(float x) {
    float y;
    asm("ex2.approx.f32 %0, %1;" : "=f"(y) : "f"(x * 1.4426950408889634f));
    return y;
}
__device__ __forceinline__ void mma_tf32(float* c, const uint32_t* a, const uint32_t* b) {
    asm volatile(
        "mma.sync.aligned.m16n8k8.row.col.f32.tf32.tf32.f32 "
        "{%0,%1,%2,%3}, {%4,%5,%6,%7}, {%8,%9}, {%0,%1,%2,%3};"
        : "+f"(c[0]), "+f"(c[1]), "+f"(c[2]), "+f"(c[3])
        : "r"(a[0]), "r"(a[1]), "r"(a[2]), "r"(a[3]), "r"(b[0]), "r"(b[1]));
}

// ============ omega pre-split (once per launch) ==========================
__global__ void k_omsplit(const float* __restrict__ omega) {
    int idx = blockIdx.x * 256 + threadIdx.x;
    if (idx >= H_ * 8 * M_ * 4) return;
    int tg = idx & 3;
    int m  = (idx >> 2) & 255;
    int ks = (idx >> 10) & 7;
    int h  = idx >> 13;
    const float* row = omega + ((size_t)h * M_ + m) * DK_ + ks * 8;
    uint32_t h0, l0, h1, l1;
    tf32_split(row[tg], h0, l0);
    tf32_split(row[tg + 4], h1, l1);
    g_omf[idx] = make_uint4(h0, h1, l0, l1);
}

// ====== weight pre-split into the Spart arena: [col][ks(128)][tg(4)] =====
__global__ void k_wsplit(const float* __restrict__ W, int ncols) {
    uint4* dst = (uint4*)g_Spart;
    int idx = blockIdx.x * 256 + threadIdx.x;
    if (idx >= ncols * 512) return;             // 128 ks * 4 tg per col
    int tg = idx & 3;
    int ks = (idx >> 2) & 127;
    int n  = idx >> 9;
    const float* row = W + (size_t)n * 1024 + ks * 8;
    uint32_t h0, l0, h1, l1;
    tf32_split(row[tg], h0, l0);
    tf32_split(row[tg + 4], h1, l1);
    dst[idx] = make_uint4(h0, h1, l0, l1);
}

// ===== mma.sync TF32 3x GEMM: A smem-staged, B direct from Spart arena ===
__global__ __launch_bounds__(256) void k_gemm_mma(const float* __restrict__ A,
                                                  const float* __restrict__ bias,
                                                  float* __restrict__ Cp,
                                                  int mode) {
    __shared__ __align__(16) float As[2][128][20];
    const int t = threadIdx.x;
    const int lane = t & 31, wid = t >> 5;
    const int g = lane >> 2, tg = lane & 3;
    const int wm = wid >> 2, wn = wid & 3;
    const int rb = blockIdx.y * 128, cb = blockIdx.x * 128;
    constexpr int K = 1024;
    constexpr int NSLAB = K / 16;
    const float* Ap = (mode == 1) ? (const float*)g_ctx : A;
    const uint4* wf = (const uint4*)g_Spart;

    float acc[4][4][4];
#pragma unroll
    for (int i = 0; i < 4; i++)
#pragma unroll
        for (int j = 0; j < 4; j++)
#pragma unroll
            for (int e = 0; e < 4; e++) acc[i][j][e] = 0.0f;

    // per-warp B fragment element offsets (uint32; max 1.57M, fits)
    uint32_t wb[4];
#pragma unroll
    for (int j = 0; j < 4; j++)
        wb[j] = ((uint32_t)(cb + wn * 32 + j * 8 + g) << 9) + (uint32_t)tg;

    {
#pragma unroll
        for (int it = 0; it < 2; it++) {
            int f = it * 256 + t;
            int r = f >> 2, q = f & 3;
            cp_async16(&As[0][r][q * 4], Ap + (size_t)(rb + r) * K + q * 4);
        }
        asm volatile("cp.async.commit_group;" ::: "memory");
    }

    for (int sl = 0; sl < NSLAB; sl++) {
        const int st = sl & 1;
        if (sl + 1 < NSLAB) {
            const int kt = (sl + 1) * 16;
            const int ns = st ^ 1;
#pragma unroll
            for (int it = 0; it < 2; it++) {
                int f = it * 256 + t;
                int r = f >> 2, q = f & 3;
                cp_async16(&As[ns][r][q * 4], Ap + (size_t)(rb + r) * K + kt + q * 4);
            }
            asm volatile("cp.async.commit_group;" ::: "memory");
            asm volatile("cp.async.wait_group 1;" ::: "memory");
        } else {
            asm volatile("cp.async.wait_group 0;" ::: "memory");
        }
        __syncthreads();

#pragma unroll
        for (int ks = 0; ks < 2; ks++) {
            const int k0 = ks * 8;
            const uint32_t ko = (uint32_t)(sl * 2 + ks) * 4;
            uint32_t ah[4][4], al[4][4], bh[4][2], bl[4][2];
#pragma unroll
            for (int j = 0; j < 4; j++) {       // scoped B fragment load
                uint4 wv = wf[wb[j] + ko];
                bh[j][0] = wv.x; bh[j][1] = wv.y;
                bl[j][0] = wv.z; bl[j][1] = wv.w;
            }
#pragma unroll
            for (int i = 0; i < 4; i++) {
                const int m0 = wm * 64 + i * 16;
                tf32_split(As[st][m0 + g    ][k0 + tg    ], ah[i][0], al[i][0]);
                tf32_split(As[st][m0 + g + 8][k0 + tg    ], ah[i][1], al[i][1]);
                tf32_split(As[st][m0 + g    ][k0 + tg + 4], ah[i][2], al[i][2]);
                tf32_split(As[st][m0 + g + 8][k0 + tg + 4], ah[i][3], al[i][3]);
            }
#pragma unroll
            for (int i = 0; i < 4; i++)
#pragma unroll
                for (int j = 0; j < 4; j++) mma_tf32(acc[i][j], ah[i], bh[j]);
#pragma unroll
            for (int i = 0; i < 4; i++)
#pragma unroll
                for (int j = 0; j < 4; j++) mma_tf32(acc[i][j], ah[i], bl[j]);
#pragma unroll
            for (int i = 0; i < 4; i++)
#pragma unroll
                for (int j = 0; j < 4; j++) mma_tf32(acc[i][j], al[i], bh[j]);
        }
        __syncthreads();
    }

#pragma unroll
    for (int i = 0; i < 4; i++) {
        const int r0 = rb + wm * 64 + i * 16 + g;
#pragma unroll
        for (int j = 0; j < 4; j++) {
            const int c = cb + wn * 32 + j * 8 + tg * 2;
            const float b0 = bias[c], b1 = bias[c + 1];
            if (mode == 1) {
                *(float2*)(Cp + (size_t)r0 * 1024 + c) =
                    make_float2(acc[i][j][0] + b0, acc[i][j][1] + b1);
                *(float2*)(Cp + (size_t)(r0 + 8) * 1024 + c) =
                    make_float2(acc[i][j][2] + b0, acc[i][j][3] + b1);
            } else {
                const int which = c >> 10;
                const int hh = (c & 1023) >> 6;
                const int dk = c & 63;
#pragma unroll
                for (int half = 0; half < 2; half++) {
                    const int r = r0 + half * 8;
                    const float vv = g_valid[r];
                    const float v0 = acc[i][j][half * 2 + 0] + b0;
                    const float v1 = acc[i][j][half * 2 + 1] + b1;
                    size_t off = ((((size_t)(r >> 12)) * H_ + hh) * N_ + (r & 4095)) * DK_ + dk;
                    if (which == 0)
                        *(float2*)(g_Q + off) = make_float2(v0 * vv, v1 * vv);
                    else if (which == 1)
                        *(float2*)(g_K + off) = make_float2(v0, v1);
                    else
                        *(float2*)(g_V + off) = make_float2(v0 * vv, v1 * vv);
                }
            }
        }
    }
}

// ===================== kernel 0: mask -> valid ==========================
__global__ void k_mask(const void* __restrict__ mask) {
    __shared__ int sF, sOdd;
    const int t = threadIdx.x;
    if (t == 0) { sF = 0; sOdd = 0; }
    __syncthreads();
    const unsigned* w = (const unsigned*)mask;
    for (int i = t; i < 4096; i += 256) {
        unsigned v = w[i];
        if (v == 0x3F800000u) sF = 1;
        else if (v != 0u && v != 1u) sOdd = 1;
    }
    __syncthreads();
    if (sF) {
        const float* m = (const float*)mask;
        for (int i = t; i < B_ * N_; i += 256)
            g_valid[i] = (m[i] != 0.0f) ? 0.0f : 1.0f;
    } else if (sOdd) {
        const unsigned char* m = (const unsigned char*)mask;
        for (int i = t; i < B_ * N_; i += 256)
            g_valid[i] = m[i] ? 0.0f : 1.0f;
    } else {
        const int* m = (const int*)mask;
        for (int i = t; i < B_ * N_; i += 256)
            g_valid[i] = m[i] ? 0.0f : 1.0f;
    }
}

// ====== kernel A: phi(K) fused with S/Ksum partial accumulation =========
__global__ __launch_bounds__(256) void k_phik_spart() {
    __shared__ __align__(16) float pool[10752];   // 43 KB
    __shared__ float s_max[4][64];
    __shared__ float s_sq[64];
    float* Ts  = pool;            // [64][36] (phi phase)
    float* Stg = pool;            // [32][264] alias
    float* Vs  = pool + 8448;     // [32][72]

    const int t = threadIdx.x, lane = t & 31, wid = t >> 5;
    const int g = lane >> 2, tg = lane & 3;
    const int wm = wid >> 2, wn = wid & 3;       // phi warp grid 2m x 4n
    const int wmA = wid >> 1, wnA = wid & 1;     // spart warp grid 4m x 2n
    const int bh = blockIdx.x, ch = blockIdx.y;
    const int h = bh & (H_ - 1), bI = bh >> 4;
    const float invs = rsqrtf(256.0f + 1e-6f);

    float acc2[4][4][4];
#pragma unroll
    for (int i = 0; i < 4; i++)
#pragma unroll
        for (int j = 0; j < 4; j++)
#pragma unroll
            for (int e = 0; e < 4; e++) acc2[i][j][e] = 0.0f;
    float ksacc = 0.0f;

    for (int tile = 0; tile < 4; tile++) {
        const int n0 = ch * 256 + tile * 64;
        float acc[2][8][4];
#pragma unroll
        for (int mi = 0; mi < 2; mi++)
#pragma unroll
            for (int nj = 0; nj < 8; nj++)
#pragma unroll
                for (int e = 0; e < 4; e++) acc[mi][nj][e] = 0.0f;

        for (int kp = 0; kp < 2; kp++) {
            const int k0g = kp * 32;
            __syncthreads();
#pragma unroll
            for (int it = 0; it < 2; it++) {
                int f = it * 256 + t;
                int r = f >> 3, q = f & 7;
                float4 v = *(const float4*)(g_K + ((size_t)bh * N_ + n0 + r) * DK_ + k0g + q * 4);
                *(float4*)(Ts + r * 36 + q * 4) = v;
            }
            __syncthreads();
            if (t < 64) {
                float ssum = 0.0f;
#pragma unroll
                for (int k = 0; k < 32; k++) { float q = Ts[t * 36 + k]; ssum += q * q; }
                if (kp == 0) s_sq[t] = ssum; else s_sq[t] += ssum;
            }
#pragma unroll
            for (int ks = 0; ks < 4; ks++) {
                const int k0 = ks * 8;
                const uint4* pb = g_omf + ((size_t)(h * 8 + kp * 4 + ks) << 10);
                uint32_t ah[2][4], al[2][4], obh[8][2], obl[8][2];
#pragma unroll
                for (int mi = 0; mi < 2; mi++) {
                    const int m0 = wm * 32 + mi * 16;
                    tf32_split(Ts[(m0 + g    ) * 36 + k0 + tg    ], ah[mi][0], al[mi][0]);
                    tf32_split(Ts[(m0 + g + 8) * 36 + k0 + tg    ], ah[mi][1], al[mi][1]);
                    tf32_split(Ts[(m0 + g    ) * 36 + k0 + tg + 4], ah[mi][2], al[mi][2]);
                    tf32_split(Ts[(m0 + g + 8) * 36 + k0 + tg + 4], ah[mi][3], al[mi][3]);
                }
#pragma unroll
                for (int nj = 0; nj < 8; nj++) {
                    uint4 v = pb[(wn * 64 + nj * 8 + g) * 4 + tg];
                    obh[nj][0] = v.x; obh[nj][1] = v.y;
                    obl[nj][0] = v.z; obl[nj][1] = v.w;
                }
#pragma unroll
                for (int mi = 0; mi < 2; mi++)
#pragma unroll
                    for (int nj = 0; nj < 8; nj++) mma_tf32(acc[mi][nj], ah[mi], obh[nj]);
#pragma unroll
                for (int mi = 0; mi < 2; mi++)
#pragma unroll
                    for (int nj = 0; nj < 8; nj++) mma_tf32(acc[mi][nj], ah[mi], obl[nj]);
#pragma unroll
                for (int mi = 0; mi < 2; mi++)
#pragma unroll
                    for (int nj = 0; nj < 8; nj++) mma_tf32(acc[mi][nj], al[mi], obh[nj]);
            }
        }
#pragma unroll
        for (int mi = 0; mi < 2; mi++) {
#pragma unroll
            for (int half = 0; half < 2; half++) {
                float m = acc[mi][0][half * 2];
#pragma unroll
                for (int nj = 0; nj < 8; nj++) {
                    m = fmaxf(m, acc[mi][nj][half * 2]);
                    m = fmaxf(m, acc[mi][nj][half * 2 + 1]);
                }
                m = fmaxf(m, __shfl_xor_sync(0xffffffffu, m, 1));
                m = fmaxf(m, __shfl_xor_sync(0xffffffffu, m, 2));
                if (tg == 0) s_max[wn][wm * 32 + mi * 16 + half * 8 + g] = m;
            }
        }
        __syncthreads();

        for (int hr = 0; hr < 2; hr++) {
            if (wm == hr) {
#pragma unroll
                for (int mi = 0; mi < 2; mi++)
#pragma unroll
                for (int half = 0; half < 2; half++) {
                    const int rloc = mi * 16 + half * 8 + g;
                    const int rg = hr * 32 + rloc;
                    float rm = fmaxf(fmaxf(s_max[0][rg], s_max[1][rg]),
                                     fmaxf(s_max[2][rg], s_max[3][rg]));
                    float e = -rm - 0.5f * s_sq[rg];
                    float sc = invs * g_valid[bI * N_ + n0 + rg];
#pragma unroll
                    for (int nj = 0; nj < 8; nj++) {
                        const int col = wn * 64 + nj * 8 + tg * 2;
                        *(float2*)(Stg + rloc * 264 + col) = make_float2(
                            tf32r(fexp(acc[mi][nj][half * 2    ] + e) * sc),
                            tf32r(fexp(acc[mi][nj][half * 2 + 1] + e) * sc));
                    }
                }
            }
#pragma unroll
            for (int it = 0; it < 2; it++) {
                int f = it * 256 + t;
                int r = f >> 4, dq = f & 15;
                float4 v = *(const float4*)(g_V + ((size_t)bh * N_ + n0 + hr * 32 + r) * DK_ + dq * 4);
                v.x = tf32r(v.x); v.y = tf32r(v.y);
                v.z = tf32r(v.z); v.w = tf32r(v.w);
                *(float4*)(Vs + r * 72 + dq * 4) = v;
            }
            __syncthreads();
#pragma unroll 8
            for (int r = 0; r < 32; r++) ksacc += Stg[r * 264 + t];
#pragma unroll
            for (int ks = 0; ks < 4; ks++) {
                const int k0 = ks * 8;
                uint32_t ah[4][4], bhf[4][2];
#pragma unroll
                for (int mi = 0; mi < 4; mi++) {
                    const int m0 = wmA * 64 + mi * 16;
                    ah[mi][0] = __float_as_uint(Stg[(k0 + tg    ) * 264 + m0 + g    ]);
                    ah[mi][1] = __float_as_uint(Stg[(k0 + tg    ) * 264 + m0 + g + 8]);
                    ah[mi][2] = __float_as_uint(Stg[(k0 + tg + 4) * 264 + m0 + g    ]);
                    ah[mi][3] = __float_as_uint(Stg[(k0 + tg + 4) * 264 + m0 + g + 8]);
                }
#pragma unroll
                for (int nj = 0; nj < 4; nj++) {
                    const int n0d = wnA * 32 + nj * 8;
                    bhf[nj][0] = __float_as_uint(Vs[(k0 + tg    ) * 72 + n0d + g]);
                    bhf[nj][1] = __float_as_uint(Vs[(k0 + tg + 4) * 72 + n0d + g]);
                }
#pragma unroll
                for (int mi = 0; mi < 4; mi++)
#pragma unroll
                    for (int nj = 0; nj < 4; nj++) mma_tf32(acc2[mi][nj], ah[mi], bhf[nj]);
            }
            __syncthreads();
        }
    }

    const size_t pb = ((size_t)bh * CH_ + ch) * M_;
#pragma unroll
    for (int mi = 0; mi < 4; mi++) {
        const int feat = wmA * 64 + mi * 16 + g;
#pragma unroll
        for (int nj = 0; nj < 4; nj++) {
            const int dk = wnA * 32 + nj * 8 + tg * 2;
            *(float2*)(g_Spart + (pb + feat) * DK_ + dk) =
                make_float2(acc2[mi][nj][0], acc2[mi][nj][1]);
            *(float2*)(g_Spart + (pb + feat + 8) * DK_ + dk) =
                make_float2(acc2[mi][nj][2], acc2[mi][nj][3]);
        }
    }
    g_Kpart[pb + t] = ksacc;
}

// ============ kernel 3b: deterministic chunk reduction ===================
__global__ void k_sreduce() {
    const int tot = BH_ * M_ * (DK_ + 1);
    int idx = blockIdx.x * 256 + threadIdx.x;
    if (idx >= tot) return;
    int bh  = idx / (M_ * (DK_ + 1));
    int rem = idx % (M_ * (DK_ + 1));
    int m = rem / (DK_ + 1);
    int d = rem % (DK_ + 1);
    if (d < DK_) {
        float s = 0.0f;
#pragma unroll
        for (int c = 0; c < CH_; c++)
            s += g_Spart[(((size_t)bh * CH_ + c) * M_ + m) * DK_ + d];
        g_S[((size_t)bh * M_ + m) * DK_ + d] = s;
    } else {
        float s = 0.0f;
#pragma unroll
        for (int c = 0; c < CH_; c++)
            s += g_Kpart[((size_t)bh * CH_ + c) * M_ + m];
        g_Ksum[(size_t)bh * M_ + m] = s;
    }
}

// ====== kernel B: phi(Q) fused with ctx = (Qf S)/(Qf Ksum + eps) ========
__global__ __launch_bounds__(256) void k_phiq_ctx() {
    __shared__ __align__(16) float pool[8960];    // 35.8 KB
    __shared__ float s_max[4][64];
    __shared__ float s_sq[64];
    __shared__ float s_den[64];
    __shared__ float Kss[64];
    float* Ts  = pool;            // [64][36]
    float* Stg = pool;            // [64][68] alias
    float* Ss  = pool + 4352;     // [64][72]

    const int t = threadIdx.x, lane = t & 31, wid = t >> 5;
    const int g = lane >> 2, tg = lane & 3;
    const int wm = wid >> 2, wn = wid & 3;
    const int bh = blockIdx.x;
    const int n0 = blockIdx.y * 64;
    const int h = bh & (H_ - 1), bI = bh >> 4;
    const float invs = rsqrtf(256.0f + 1e-6f);

    float acc[2][8][4];
#pragma unroll
    for (int mi = 0; mi < 2; mi++)
#pragma unroll
        for (int nj = 0; nj < 8; nj++)
#pragma unroll
            for (int e = 0; e < 4; e++) acc[mi][nj][e] = 0.0f;
    float accC[2][2][4];
#pragma unroll
    for (int mi = 0; mi < 2; mi++)
#pragma unroll
        for (int nj = 0; nj < 2; nj++)
#pragma unroll
            for (int e = 0; e < 4; e++) accC[mi][nj][e] = 0.0f;
    float dpart = 0.0f;

    for (int kp = 0; kp < 2; kp++) {
        const int k0g = kp * 32;
        __syncthreads();
#pragma unroll
        for (int it = 0; it < 2; it++) {
            int f = it * 256 + t;
            int r = f >> 3, q = f & 7;
            float4 v = *(const float4*)(g_Q + ((size_t)bh * N_ + n0 + r) * DK_ + k0g + q * 4);
            *(float4*)(Ts + r * 36 + q * 4) = v;
        }
        __syncthreads();
        if (t < 64) {
            float ssum = 0.0f;
#pragma unroll
            for (int k = 0; k < 32; k++) { float q = Ts[t * 36 + k]; ssum += q * q; }
            if (kp == 0) s_sq[t] = ssum; else s_sq[t] += ssum;
        }
#pragma unroll
        for (int ks = 0; ks < 4; ks++) {
            const int k0 = ks * 8;
            const uint4* pb = g_omf + ((size_t)(h * 8 + kp * 4 + ks) << 10);
            uint32_t ah[2][4], al[2][4], obh[8][2], obl[8][2];
#pragma unroll
            for (int mi = 0; mi < 2; mi++) {
                const int m0 = wm * 32 + mi * 16;
                tf32_split(Ts[(m0 + g    ) * 36 + k0 + tg    ], ah[mi][0], al[mi][0]);
                tf32_split(Ts[(m0 + g + 8) * 36 + k0 + tg    ], ah[mi][1], al[mi][1]);
                tf32_split(Ts[(m0 + g    ) * 36 + k0 + tg + 4], ah[mi][2], al[mi][2]);
                tf32_split(Ts[(m0 + g + 8) * 36 + k0 + tg + 4], ah[mi][3], al[mi][3]);
            }
#pragma unroll
            for (int nj = 0; nj < 8; nj++) {
                uint4 v = pb[(wn * 64 + nj * 8 + g) * 4 + tg];
                obh[nj][0] = v.x; obh[nj][1] = v.y;
                obl[nj][0] = v.z; obl[nj][1] = v.w;
            }
#pragma unroll
            for (int mi = 0; mi < 2; mi++)
#pragma unroll
                for (int nj = 0; nj < 8; nj++) mma_tf32(acc[mi][nj], ah[mi], obh[nj]);
#pragma unroll
            for (int mi = 0; mi < 2; mi++)
#pragma unroll
                for (int nj = 0; nj < 8; nj++) mma_tf32(acc[mi][nj], ah[mi], obl[nj]);
#pragma unroll
            for (int mi = 0; mi < 2; mi++)
#pragma unroll
                for (int nj = 0; nj < 8; nj++) mma_tf32(acc[mi][nj], al[mi], obh[nj]);
        }
    }
#pragma unroll
    for (int mi = 0; mi < 2; mi++) {
#pragma unroll
        for (int half = 0; half < 2; half++) {
            float m = acc[mi][0][half * 2];
#pragma unroll
            for (int nj = 0; nj < 8; nj++) {
                m = fmaxf(m, acc[mi][nj][half * 2]);
                m = fmaxf(m, acc[mi][nj][half * 2 + 1]);
            }
            m = fmaxf(m, __shfl_xor_sync(0xffffffffu, m, 1));
            m = fmaxf(m, __shfl_xor_sync(0xffffffffu, m, 2));
            if (tg == 0) s_max[wn][wm * 32 + mi * 16 + half * 8 + g] = m;
        }
    }
    __syncthreads();

    for (int s = 0; s < 4; s++) {
        if (s) __syncthreads();
        if (wn == s) {
#pragma unroll
            for (int mi = 0; mi < 2; mi++)
#pragma unroll
            for (int half = 0; half < 2; half++) {
                const int rg = wm * 32 + mi * 16 + half * 8 + g;
                float rm = fmaxf(fmaxf(s_max[0][rg], s_max[1][rg]),
                                 fmaxf(s_max[2][rg], s_max[3][rg]));
                float e = -rm - 0.5f * s_sq[rg];
#pragma unroll
                for (int nj = 0; nj < 8; nj++) {
                    const int col = nj * 8 + tg * 2;
                    *(float2*)(Stg + rg * 68 + col) = make_float2(
                        tf32r(fexp(acc[mi][nj][half * 2    ] + e) * invs),
                        tf32r(fexp(acc[mi][nj][half * 2 + 1] + e) * invs));
                }
            }
        }
#pragma unroll
        for (int it = 0; it < 4; it++) {
            int f = it * 256 + t;
            int r = f >> 4, dq = f & 15;
            float4 v = *(const float4*)(g_S + ((size_t)bh * M_ + s * 64 + r) * DK_ + dq * 4);
            v.x = tf32r(v.x); v.y = tf32r(v.y);
            v.z = tf32r(v.z); v.w = tf32r(v.w);
            *(float4*)(Ss + r * 72 + dq * 4) = v;
        }
        if (t < 64) Kss[t] = g_Ksum[(size_t)bh * M_ + s * 64 + t];
        __syncthreads();
        {
            const int r = t >> 2, fg = (t & 3) * 16;
#pragma unroll
            for (int i = 0; i < 16; i++)
                dpart = fmaf(Stg[r * 68 + fg + i], Kss[fg + i], dpart);
        }
#pragma unroll
        for (int ks = 0; ks < 8; ks++) {
            const int k0 = ks * 8;
            uint32_t ah[2][4], bhf[2][2];
#pragma unroll
            for (int mi = 0; mi < 2; mi++) {
                const int m0 = wm * 32 + mi * 16;
                ah[mi][0] = __float_as_uint(Stg[(m0 + g    ) * 68 + k0 + tg    ]);
                ah[mi][1] = __float_as_uint(Stg[(m0 + g + 8) * 68 + k0 + tg    ]);
                ah[mi][2] = __float_as_uint(Stg[(m0 + g    ) * 68 + k0 + tg + 4]);
                ah[mi][3] = __float_as_uint(Stg[(m0 + g + 8) * 68 + k0 + tg + 4]);
            }
#pragma unroll
            for (int nj = 0; nj < 2; nj++) {
                const int n0d = wn * 16 + nj * 8;
                bhf[nj][0] = __float_as_uint(Ss[(k0 + tg    ) * 72 + n0d + g]);
                bhf[nj][1] = __float_as_uint(Ss[(k0 + tg + 4) * 72 + n0d + g]);
            }
#pragma unroll
            for (int mi = 0; mi < 2; mi++)
#pragma unroll
                for (int nj = 0; nj < 2; nj++) mma_tf32(accC[mi][nj], ah[mi], bhf[nj]);
        }
    }
    dpart += __shfl_xor_sync(0xffffffffu, dpart, 1);
    dpart += __shfl_xor_sync(0xffffffffu, dpart, 2);
    if ((t & 3) == 0) s_den[t >> 2] = dpart;
    __syncthreads();

#pragma unroll
    for (int mi = 0; mi < 2; mi++) {
        const int r0 = wm * 32 + mi * 16 + g;
#pragma unroll
        for (int nj = 0; nj < 2; nj++) {
            const int dk = wn * 16 + nj * 8 + tg * 2;
#pragma unroll
            for (int half = 0; half < 2; half++) {
                const int r = r0 + half * 8;
                const float vv = g_valid[bI * N_ + n0 + r];
                const float dn = vv / (s_den[r] + 1e-6f);
                *(float2*)(g_ctx + ((size_t)bI * N_ + n0 + r) * D_ + h * DK_ + dk) =
                    make_float2(accC[mi][nj][half * 2] * dn,
                                accC[mi][nj][half * 2 + 1] * dn);
            }
        }
    }
}

// ========================= launch ========================================
extern "C" void kernel_launch(void* const* d_in, const int* in_sizes, int n_in,
                              void* d_out, int out_size) {
    (void)in_sizes; (void)n_in; (void)out_size;
    const float* x     = (const float*)d_in[0];
    const float* Wqkv  = (const float*)d_in[1];
    const float* bqkv  = (const float*)d_in[2];
    const float* Wout  = (const float*)d_in[3];
    const float* bout  = (const float*)d_in[4];
    const float* omega = (const float*)d_in[5];
    const void*  mask  = d_in[6];
    float* out = (float*)d_out;

    k_mask<<<1, 256>>>(mask);
    k_omsplit<<<512, 256>>>(omega);
    // Wqkv fragments -> Spart arena (Spart not yet live)
    k_wsplit<<<(3072 * 512 + 255) / 256, 256>>>(Wqkv, 3072);
    k_gemm_mma<<<dim3(24, 128), 256>>>(x, bqkv, nullptr, 0);
    k_phik_spart<<<dim3(BH_, CH_), 256>>>();        // overwrites arena
    {
        const int tot = BH_ * M_ * (DK_ + 1);
        k_sreduce<<<(tot + 255) / 256, 256>>>();    // Spart dead after this
    }
    // Wout fragments -> Spart arena (reuse)
    k_wsplit<<<(1024 * 512 + 255) / 256, 256>>>(Wout, 1024);
    k_phiq_ctx<<<dim3(BH_, N_ / 64), 256>>>();
    k_gemm_mma<<<dim3(8, 128), 256>>>(x, bout, out, 1);
}

// round 16
// speedup vs baseline: 1.1794x; 1.1794x over previous
#include <cuda_runtime.h>
#include <cstdint>
#include <math.h>

// FAVOR+ attention  B=4,N=4096,D=1024,H=16,dk=64,M=256
// R16 = R12 (best passing, 3188us) with ONE change: OUT projection
// (mode==1, post-exp linear algebra) demoted to tf32-1x — same validated
// precision class as the R12 spart/ctx demotion. QKV GEMM stays 3x (feeds
// exp). R13-R15's weight-pre-split GEMM reverted (regressed: 4x B traffic
// + exposed L2 latency beat the split savings).

namespace {
constexpr int B_  = 4;
constexpr int N_  = 4096;
constexpr int D_  = 1024;
constexpr int H_  = 16;
constexpr int DK_ = 64;
constexpr int M_  = 256;
constexpr int BH_ = B_ * H_;
constexpr int CH_ = 16;
}

// -------- device scratch --------
__device__ float g_valid[B_ * N_];
__device__ float g_Q[BH_ * N_ * DK_];
__device__ float g_K[BH_ * N_ * DK_];
__device__ float g_V[BH_ * N_ * DK_];
__device__ float g_Spart[(size_t)BH_ * CH_ * M_ * DK_];
__device__ float g_Kpart[BH_ * CH_ * M_];
__device__ float g_S[BH_ * M_ * DK_];
__device__ float g_Ksum[BH_ * M_];
__device__ float g_ctx[(size_t)B_ * N_ * D_];
// omega pre-split, fragment layout: [h][ks(8)][m(256)][tg(4)] uint4
__device__ uint4 g_omf[H_ * 8 * M_ * 4];

// ---- helpers ----
__device__ __forceinline__ uint32_t smem_u32(const void* p) {
    uint32_t a;
    asm("{ .reg .u64 t; cvta.to.shared.u64 t, %1; cvt.u32.u64 %0, t; }"
        : "=r"(a) : "l"(p));
    return a;
}
__device__ __forceinline__ void cp_async16(void* sdst, const void* gsrc) {
    asm volatile("cp.async.cg.shared.global [%0], [%1], 16;"
                 :: "r"(smem_u32(sdst)), "l"(gsrc) : "memory");
}
__device__ __forceinline__ void tf32_split(float f, uint32_t& h, uint32_t& l) {
    uint32_t hb;
    asm("cvt.rna.tf32.f32 %0, %1;" : "=r"(hb) : "f"(f));
    float lf = f - __uint_as_float(hb);
    uint32_t lb;
    asm("cvt.rna.tf32.f32 %0, %1;" : "=r"(lb) : "f"(lf));
    h = hb; l = lb;
}
__device__ __forceinline__ uint32_t tf32h(float f) {  // rna-rounded bits
    uint32_t hb;
    asm("cvt.rna.tf32.f32 %0, %1;" : "=r"(hb) : "f"(f));
    return hb;
}
__device__ __forceinline__ float tf32r(float f) {
    return __uint_as_float(tf32h(f));
}
__device__ __forceinline__ float fexp(float x) {
    float y;
    asm("ex2.approx.f32 %0, %1;" : "=f"(y) : "f"(x * 1.4426950408889634f));
    return y;
}
__device__ __forceinline__ void mma_tf32(float* c, const uint32_t* a, const uint32_t* b) {
    asm volatile(
        "mma.sync.aligned.m16n8k8.row.col.f32.tf32.tf32.f32 "
        "{%0,%1,%2,%3}, {%4,%5,%6,%7}, {%8,%9}, {%0,%1,%2,%3};"
        : "+f"(c[0]), "+f"(c[1]), "+f"(c[2]), "+f"(c[3])
        : "r"(a[0]), "r"(a[1]), "r"(a[2]), "r"(a[3]), "r"(b[0]), "r"(b[1]));
}

// ============ omega pre-split (once per launch) ==========================
__global__ void k_omsplit(const float* __restrict__ omega) {
    int idx = blockIdx.x * 256 + threadIdx.x;
    if (idx >= H_ * 8 * M_ * 4) return;
    int tg = idx & 3;
    int m  = (idx >> 2) & 255;
    int ks = (idx >> 10) & 7;
    int h  = idx >> 13;
    const float* row = omega + ((size_t)h * M_ + m) * DK_ + ks * 8;
    uint32_t h0, l0, h1, l1;
    tf32_split(row[tg], h0, l0);
    tf32_split(row[tg + 4], h1, l1);
    g_omf[idx] = make_uint4(h0, h1, l0, l1);
}

// ============ mma.sync TF32 GEMM: mode 0 = 3x (QKV), mode 1 = 1x (OUT) ===
__global__ __launch_bounds__(256) void k_gemm_mma(const float* __restrict__ A,
                                                  const float* __restrict__ Bw,
                                                  const float* __restrict__ bias,
                                                  float* __restrict__ Cp,
                                                  int mode) {
    __shared__ __align__(16) float As[2][128][20];
    __shared__ __align__(16) float Bs[2][128][20];
    const int t = threadIdx.x;
    const int lane = t & 31, wid = t >> 5;
    const int g = lane >> 2, tg = lane & 3;
    const int wm = wid >> 2, wn = wid & 3;
    const int rb = blockIdx.y * 128, cb = blockIdx.x * 128;
    constexpr int K = 1024;
    constexpr int NSLAB = K / 16;
    const float* Ap = (mode == 1) ? (const float*)g_ctx : A;

    float acc[4][4][4];
#pragma unroll
    for (int i = 0; i < 4; i++)
#pragma unroll
        for (int j = 0; j < 4; j++)
#pragma unroll
            for (int e = 0; e < 4; e++) acc[i][j][e] = 0.0f;

    {
#pragma unroll
        for (int it = 0; it < 2; it++) {
            int f = it * 256 + t;
            int r = f >> 2, q = f & 3;
            cp_async16(&As[0][r][q * 4], Ap + (size_t)(rb + r) * K + q * 4);
            cp_async16(&Bs[0][r][q * 4], Bw + (size_t)(cb + r) * K + q * 4);
        }
        asm volatile("cp.async.commit_group;" ::: "memory");
    }

    for (int sl = 0; sl < NSLAB; sl++) {
        const int st = sl & 1;
        if (sl + 1 < NSLAB) {
            const int kt = (sl + 1) * 16;
            const int ns = st ^ 1;
#pragma unroll
            for (int it = 0; it < 2; it++) {
                int f = it * 256 + t;
                int r = f >> 2, q = f & 3;
                cp_async16(&As[ns][r][q * 4], Ap + (size_t)(rb + r) * K + kt + q * 4);
                cp_async16(&Bs[ns][r][q * 4], Bw + (size_t)(cb + r) * K + kt + q * 4);
            }
            asm volatile("cp.async.commit_group;" ::: "memory");
            asm volatile("cp.async.wait_group 1;" ::: "memory");
        } else {
            asm volatile("cp.async.wait_group 0;" ::: "memory");
        }
        __syncthreads();

        if (mode == 0) {       // 3x: QKV projection (feeds exp -> precise)
#pragma unroll
            for (int ks = 0; ks < 2; ks++) {
                const int k0 = ks * 8;
                uint32_t ah[4][4], al[4][4], bh[4][2], bl[4][2];
#pragma unroll
                for (int i = 0; i < 4; i++) {
                    const int m0 = wm * 64 + i * 16;
                    tf32_split(As[st][m0 + g    ][k0 + tg    ], ah[i][0], al[i][0]);
                    tf32_split(As[st][m0 + g + 8][k0 + tg    ], ah[i][1], al[i][1]);
                    tf32_split(As[st][m0 + g    ][k0 + tg + 4], ah[i][2], al[i][2]);
                    tf32_split(As[st][m0 + g + 8][k0 + tg + 4], ah[i][3], al[i][3]);
                }
#pragma unroll
                for (int j = 0; j < 4; j++) {
                    const int n0 = wn * 32 + j * 8;
                    tf32_split(Bs[st][n0 + g][k0 + tg    ], bh[j][0], bl[j][0]);
                    tf32_split(Bs[st][n0 + g][k0 + tg + 4], bh[j][1], bl[j][1]);
                }
#pragma unroll
                for (int i = 0; i < 4; i++)
#pragma unroll
                    for (int j = 0; j < 4; j++) mma_tf32(acc[i][j], ah[i], bh[j]);
#pragma unroll
                for (int i = 0; i < 4; i++)
#pragma unroll
                    for (int j = 0; j < 4; j++) mma_tf32(acc[i][j], ah[i], bl[j]);
#pragma unroll
                for (int i = 0; i < 4; i++)
#pragma unroll
                    for (int j = 0; j < 4; j++) mma_tf32(acc[i][j], al[i], bh[j]);
            }
        } else {               // 1x: OUT projection (post-exp linear algebra)
#pragma unroll
            for (int ks = 0; ks < 2; ks++) {
                const int k0 = ks * 8;
                uint32_t ah[4][4], bh[4][2];
#pragma unroll
                for (int i = 0; i < 4; i++) {
                    const int m0 = wm * 64 + i * 16;
                    ah[i][0] = tf32h(As[st][m0 + g    ][k0 + tg    ]);
                    ah[i][1] = tf32h(As[st][m0 + g + 8][k0 + tg    ]);
                    ah[i][2] = tf32h(As[st][m0 + g    ][k0 + tg + 4]);
                    ah[i][3] = tf32h(As[st][m0 + g + 8][k0 + tg + 4]);
                }
#pragma unroll
                for (int j = 0; j < 4; j++) {
                    const int n0 = wn * 32 + j * 8;
                    bh[j][0] = tf32h(Bs[st][n0 + g][k0 + tg    ]);
                    bh[j][1] = tf32h(Bs[st][n0 + g][k0 + tg + 4]);
                }
#pragma unroll
                for (int i = 0; i < 4; i++)
#pragma unroll
                    for (int j = 0; j < 4; j++) mma_tf32(acc[i][j], ah[i], bh[j]);
            }
        }
        __syncthreads();
    }

#pragma unroll
    for (int i = 0; i < 4; i++) {
        const int r0 = rb + wm * 64 + i * 16 + g;
#pragma unroll
        for (int j = 0; j < 4; j++) {
            const int c = cb + wn * 32 + j * 8 + tg * 2;
            const float b0 = bias[c], b1 = bias[c + 1];
            if (mode == 1) {
                *(float2*)(Cp + (size_t)r0 * 1024 + c) =
                    make_float2(acc[i][j][0] + b0, acc[i][j][1] + b1);
                *(float2*)(Cp + (size_t)(r0 + 8) * 1024 + c) =
                    make_float2(acc[i][j][2] + b0, acc[i][j][3] + b1);
            } else {
                const int which = c >> 10;
                const int hh = (c & 1023) >> 6;
                const int dk = c & 63;
#pragma unroll
                for (int half = 0; half < 2; half++) {
                    const int r = r0 + half * 8;
                    const float vv = g_valid[r];
                    const float v0 = acc[i][j][half * 2 + 0] + b0;
                    const float v1 = acc[i][j][half * 2 + 1] + b1;
                    size_t off = ((((size_t)(r >> 12)) * H_ + hh) * N_ + (r & 4095)) * DK_ + dk;
                    if (which == 0)
                        *(float2*)(g_Q + off) = make_float2(v0 * vv, v1 * vv);
                    else if (which == 1)
                        *(float2*)(g_K + off) = make_float2(v0, v1);
                    else
                        *(float2*)(g_V + off) = make_float2(v0 * vv, v1 * vv);
                }
            }
        }
    }
}

// ===================== kernel 0: mask -> valid ==========================
__global__ void k_mask(const void* __restrict__ mask) {
    __shared__ int sF, sOdd;
    const int t = threadIdx.x;
    if (t == 0) { sF = 0; sOdd = 0; }
    __syncthreads();
    const unsigned* w = (const unsigned*)mask;
    for (int i = t; i < 4096; i += 256) {
        unsigned v = w[i];
        if (v == 0x3F800000u) sF = 1;
        else if (v != 0u && v != 1u) sOdd = 1;
    }
    __syncthreads();
    if (sF) {
        const float* m = (const float*)mask;
        for (int i = t; i < B_ * N_; i += 256)
            g_valid[i] = (m[i] != 0.0f) ? 0.0f : 1.0f;
    } else if (sOdd) {
        const unsigned char* m = (const unsigned char*)mask;
        for (int i = t; i < B_ * N_; i += 256)
            g_valid[i] = m[i] ? 0.0f : 1.0f;
    } else {
        const int* m = (const int*)mask;
        for (int i = t; i < B_ * N_; i += 256)
            g_valid[i] = m[i] ? 0.0f : 1.0f;
    }
}

// ====== kernel A: phi(K) fused with S/Ksum partial accumulation =========
__global__ __launch_bounds__(256) void k_phik_spart() {
    __shared__ __align__(16) float pool[10752];   // 43 KB
    __shared__ float s_max[4][64];
    __shared__ float s_sq[64];
    float* Ts  = pool;            // [64][36] (phi phase)
    float* Stg = pool;            // [32][264] alias
    float* Vs  = pool + 8448;     // [32][72]

    const int t = threadIdx.x, lane = t & 31, wid = t >> 5;
    const int g = lane >> 2, tg = lane & 3;
    const int wm = wid >> 2, wn = wid & 3;       // phi warp grid 2m x 4n
    const int wmA = wid >> 1, wnA = wid & 1;     // spart warp grid 4m x 2n
    const int bh = blockIdx.x, ch = blockIdx.y;
    const int h = bh & (H_ - 1), bI = bh >> 4;
    const float invs = rsqrtf(256.0f + 1e-6f);

    float acc2[4][4][4];
#pragma unroll
    for (int i = 0; i < 4; i++)
#pragma unroll
        for (int j = 0; j < 4; j++)
#pragma unroll
            for (int e = 0; e < 4; e++) acc2[i][j][e] = 0.0f;
    float ksacc = 0.0f;

    for (int tile = 0; tile < 4; tile++) {
        const int n0 = ch * 256 + tile * 64;
        float acc[2][8][4];
#pragma unroll
        for (int mi = 0; mi < 2; mi++)
#pragma unroll
            for (int nj = 0; nj < 8; nj++)
#pragma unroll
                for (int e = 0; e < 4; e++) acc[mi][nj][e] = 0.0f;

        for (int kp = 0; kp < 2; kp++) {
            const int k0g = kp * 32;
            __syncthreads();
#pragma unroll
            for (int it = 0; it < 2; it++) {
                int f = it * 256 + t;
                int r = f >> 3, q = f & 7;
                float4 v = *(const float4*)(g_K + ((size_t)bh * N_ + n0 + r) * DK_ + k0g + q * 4);
                *(float4*)(Ts + r * 36 + q * 4) = v;
            }
            __syncthreads();
            if (t < 64) {
                float ssum = 0.0f;
#pragma unroll
                for (int k = 0; k < 32; k++) { float q = Ts[t * 36 + k]; ssum += q * q; }
                if (kp == 0) s_sq[t] = ssum; else s_sq[t] += ssum;
            }
#pragma unroll
            for (int ks = 0; ks < 4; ks++) {
                const int k0 = ks * 8;
                const uint4* pb = g_omf + ((size_t)(h * 8 + kp * 4 + ks) << 10);
                uint32_t ah[2][4], al[2][4], obh[8][2], obl[8][2];
#pragma unroll
                for (int mi = 0; mi < 2; mi++) {
                    const int m0 = wm * 32 + mi * 16;
                    tf32_split(Ts[(m0 + g    ) * 36 + k0 + tg    ], ah[mi][0], al[mi][0]);
                    tf32_split(Ts[(m0 + g + 8) * 36 + k0 + tg    ], ah[mi][1], al[mi][1]);
                    tf32_split(Ts[(m0 + g    ) * 36 + k0 + tg + 4], ah[mi][2], al[mi][2]);
                    tf32_split(Ts[(m0 + g + 8) * 36 + k0 + tg + 4], ah[mi][3], al[mi][3]);
                }
#pragma unroll
                for (int nj = 0; nj < 8; nj++) {
                    uint4 v = pb[(wn * 64 + nj * 8 + g) * 4 + tg];
                    obh[nj][0] = v.x; obh[nj][1] = v.y;
                    obl[nj][0] = v.z; obl[nj][1] = v.w;
                }
#pragma unroll
                for (int mi = 0; mi < 2; mi++)
#pragma unroll
                    for (int nj = 0; nj < 8; nj++) mma_tf32(acc[mi][nj], ah[mi], obh[nj]);
#pragma unroll
                for (int mi = 0; mi < 2; mi++)
#pragma unroll
                    for (int nj = 0; nj < 8; nj++) mma_tf32(acc[mi][nj], ah[mi], obl[nj]);
#pragma unroll
                for (int mi = 0; mi < 2; mi++)
#pragma unroll
                    for (int nj = 0; nj < 8; nj++) mma_tf32(acc[mi][nj], al[mi], obh[nj]);
            }
        }
#pragma unroll
        for (int mi = 0; mi < 2; mi++) {
#pragma unroll
            for (int half = 0; half < 2; half++) {
                float m = acc[mi][0][half * 2];
#pragma unroll
                for (int nj = 0; nj < 8; nj++) {
                    m = fmaxf(m, acc[mi][nj][half * 2]);
                    m = fmaxf(m, acc[mi][nj][half * 2 + 1]);
                }
                m = fmaxf(m, __shfl_xor_sync(0xffffffffu, m, 1));
                m = fmaxf(m, __shfl_xor_sync(0xffffffffu, m, 2));
                if (tg == 0) s_max[wn][wm * 32 + mi * 16 + half * 8 + g] = m;
            }
        }
        __syncthreads();

        for (int hr = 0; hr < 2; hr++) {
            if (wm == hr) {
#pragma unroll
                for (int mi = 0; mi < 2; mi++)
#pragma unroll
                for (int half = 0; half < 2; half++) {
                    const int rloc = mi * 16 + half * 8 + g;
                    const int rg = hr * 32 + rloc;
                    float rm = fmaxf(fmaxf(s_max[0][rg], s_max[1][rg]),
                                     fmaxf(s_max[2][rg], s_max[3][rg]));
                    float e = -rm - 0.5f * s_sq[rg];
                    float sc = invs * g_valid[bI * N_ + n0 + rg];
#pragma unroll
                    for (int nj = 0; nj < 8; nj++) {
                        const int col = wn * 64 + nj * 8 + tg * 2;
                        *(float2*)(Stg + rloc * 264 + col) = make_float2(
                            tf32r(fexp(acc[mi][nj][half * 2    ] + e) * sc),
                            tf32r(fexp(acc[mi][nj][half * 2 + 1] + e) * sc));
                    }
                }
            }
#pragma unroll
            for (int it = 0; it < 2; it++) {
                int f = it * 256 + t;
                int r = f >> 4, dq = f & 15;
                float4 v = *(const float4*)(g_V + ((size_t)bh * N_ + n0 + hr * 32 + r) * DK_ + dq * 4);
                v.x = tf32r(v.x); v.y = tf32r(v.y);
                v.z = tf32r(v.z); v.w = tf32r(v.w);
                *(float4*)(Vs + r * 72 + dq * 4) = v;
            }
            __syncthreads();
#pragma unroll 8
            for (int r = 0; r < 32; r++) ksacc += Stg[r * 264 + t];
#pragma unroll
            for (int ks = 0; ks < 4; ks++) {
                const int k0 = ks * 8;
                uint32_t ah[4][4], bhf[4][2];
#pragma unroll
                for (int mi = 0; mi < 4; mi++) {
                    const int m0 = wmA * 64 + mi * 16;
                    ah[mi][0] = __float_as_uint(Stg[(k0 + tg    ) * 264 + m0 + g    ]);
                    ah[mi][1] = __float_as_uint(Stg[(k0 + tg    ) * 264 + m0 + g + 8]);
                    ah[mi][2] = __float_as_uint(Stg[(k0 + tg + 4) * 264 + m0 + g    ]);
                    ah[mi][3] = __float_as_uint(Stg[(k0 + tg + 4) * 264 + m0 + g + 8]);
                }
#pragma unroll
                for (int nj = 0; nj < 4; nj++) {
                    const int n0d = wnA * 32 + nj * 8;
                    bhf[nj][0] = __float_as_uint(Vs[(k0 + tg    ) * 72 + n0d + g]);
                    bhf[nj][1] = __float_as_uint(Vs[(k0 + tg + 4) * 72 + n0d + g]);
                }
#pragma unroll
                for (int mi = 0; mi < 4; mi++)
#pragma unroll
                    for (int nj = 0; nj < 4; nj++) mma_tf32(acc2[mi][nj], ah[mi], bhf[nj]);
            }
            __syncthreads();
        }
    }

    const size_t pb = ((size_t)bh * CH_ + ch) * M_;
#pragma unroll
    for (int mi = 0; mi < 4; mi++) {
        const int feat = wmA * 64 + mi * 16 + g;
#pragma unroll
        for (int nj = 0; nj < 4; nj++) {
            const int dk = wnA * 32 + nj * 8 + tg * 2;
            *(float2*)(g_Spart + (pb + feat) * DK_ + dk) =
                make_float2(acc2[mi][nj][0], acc2[mi][nj][1]);
            *(float2*)(g_Spart + (pb + feat + 8) * DK_ + dk) =
                make_float2(acc2[mi][nj][2], acc2[mi][nj][3]);
        }
    }
    g_Kpart[pb + t] = ksacc;
}

// ============ kernel 3b: deterministic chunk reduction ===================
__global__ void k_sreduce() {
    const int tot = BH_ * M_ * (DK_ + 1);
    int idx = blockIdx.x * 256 + threadIdx.x;
    if (idx >= tot) return;
    int bh  = idx / (M_ * (DK_ + 1));
    int rem = idx % (M_ * (DK_ + 1));
    int m = rem / (DK_ + 1);
    int d = rem % (DK_ + 1);
    if (d < DK_) {
        float s = 0.0f;
#pragma unroll
        for (int c = 0; c < CH_; c++)
            s += g_Spart[(((size_t)bh * CH_ + c) * M_ + m) * DK_ + d];
        g_S[((size_t)bh * M_ + m) * DK_ + d] = s;
    } else {
        float s = 0.0f;
#pragma unroll
        for (int c = 0; c < CH_; c++)
            s += g_Kpart[((size_t)bh * CH_ + c) * M_ + m];
        g_Ksum[(size_t)bh * M_ + m] = s;
    }
}

// ====== kernel B: phi(Q) fused with ctx = (Qf S)/(Qf Ksum + eps) ========
__global__ __launch_bounds__(256) void k_phiq_ctx() {
    __shared__ __align__(16) float pool[8960];    // 35.8 KB
    __shared__ float s_max[4][64];
    __shared__ float s_sq[64];
    __shared__ float s_den[64];
    __shared__ float Kss[64];
    float* Ts  = pool;            // [64][36]
    float* Stg = pool;            // [64][68] alias
    float* Ss  = pool + 4352;     // [64][72]

    const int t = threadIdx.x, lane = t & 31, wid = t >> 5;
    const int g = lane >> 2, tg = lane & 3;
    const int wm = wid >> 2, wn = wid & 3;
    const int bh = blockIdx.x;
    const int n0 = blockIdx.y * 64;
    const int h = bh & (H_ - 1), bI = bh >> 4;
    const float invs = rsqrtf(256.0f + 1e-6f);

    float acc[2][8][4];
#pragma unroll
    for (int mi = 0; mi < 2; mi++)
#pragma unroll
        for (int nj = 0; nj < 8; nj++)
#pragma unroll
            for (int e = 0; e < 4; e++) acc[mi][nj][e] = 0.0f;
    float accC[2][2][4];
#pragma unroll
    for (int mi = 0; mi < 2; mi++)
#pragma unroll
        for (int nj = 0; nj < 2; nj++)
#pragma unroll
            for (int e = 0; e < 4; e++) accC[mi][nj][e] = 0.0f;
    float dpart = 0.0f;

    for (int kp = 0; kp < 2; kp++) {
        const int k0g = kp * 32;
        __syncthreads();
#pragma unroll
        for (int it = 0; it < 2; it++) {
            int f = it * 256 + t;
            int r = f >> 3, q = f & 7;
            float4 v = *(const float4*)(g_Q + ((size_t)bh * N_ + n0 + r) * DK_ + k0g + q * 4);
            *(float4*)(Ts + r * 36 + q * 4) = v;
        }
        __syncthreads();
        if (t < 64) {
            float ssum = 0.0f;
#pragma unroll
            for (int k = 0; k < 32; k++) { float q = Ts[t * 36 + k]; ssum += q * q; }
            if (kp == 0) s_sq[t] = ssum; else s_sq[t] += ssum;
        }
#pragma unroll
        for (int ks = 0; ks < 4; ks++) {
            const int k0 = ks * 8;
            const uint4* pb = g_omf + ((size_t)(h * 8 + kp * 4 + ks) << 10);
            uint32_t ah[2][4], al[2][4], obh[8][2], obl[8][2];
#pragma unroll
            for (int mi = 0; mi < 2; mi++) {
                const int m0 = wm * 32 + mi * 16;
                tf32_split(Ts[(m0 + g    ) * 36 + k0 + tg    ], ah[mi][0], al[mi][0]);
                tf32_split(Ts[(m0 + g + 8) * 36 + k0 + tg    ], ah[mi][1], al[mi][1]);
                tf32_split(Ts[(m0 + g    ) * 36 + k0 + tg + 4], ah[mi][2], al[mi][2]);
                tf32_split(Ts[(m0 + g + 8) * 36 + k0 + tg + 4], ah[mi][3], al[mi][3]);
            }
#pragma unroll
            for (int nj = 0; nj < 8; nj++) {
                uint4 v = pb[(wn * 64 + nj * 8 + g) * 4 + tg];
                obh[nj][0] = v.x; obh[nj][1] = v.y;
                obl[nj][0] = v.z; obl[nj][1] = v.w;
            }
#pragma unroll
            for (int mi = 0; mi < 2; mi++)
#pragma unroll
                for (int nj = 0; nj < 8; nj++) mma_tf32(acc[mi][nj], ah[mi], obh[nj]);
#pragma unroll
            for (int mi = 0; mi < 2; mi++)
#pragma unroll
                for (int nj = 0; nj < 8; nj++) mma_tf32(acc[mi][nj], ah[mi], obl[nj]);
#pragma unroll
            for (int mi = 0; mi < 2; mi++)
#pragma unroll
                for (int nj = 0; nj < 8; nj++) mma_tf32(acc[mi][nj], al[mi], obh[nj]);
        }
    }
#pragma unroll
    for (int mi = 0; mi < 2; mi++) {
#pragma unroll
        for (int half = 0; half < 2; half++) {
            float m = acc[mi][0][half * 2];
#pragma unroll
            for (int nj = 0; nj < 8; nj++) {
                m = fmaxf(m, acc[mi][nj][half * 2]);
                m = fmaxf(m, acc[mi][nj][half * 2 + 1]);
            }
            m = fmaxf(m, __shfl_xor_sync(0xffffffffu, m, 1));
            m = fmaxf(m, __shfl_xor_sync(0xffffffffu, m, 2));
            if (tg == 0) s_max[wn][wm * 32 + mi * 16 + half * 8 + g] = m;
        }
    }
    __syncthreads();

    for (int s = 0; s < 4; s++) {
        if (s) __syncthreads();
        if (wn == s) {
#pragma unroll
            for (int mi = 0; mi < 2; mi++)
#pragma unroll
            for (int half = 0; half < 2; half++) {
                const int rg = wm * 32 + mi * 16 + half * 8 + g;
                float rm = fmaxf(fmaxf(s_max[0][rg], s_max[1][rg]),
                                 fmaxf(s_max[2][rg], s_max[3][rg]));
                float e = -rm - 0.5f * s_sq[rg];
#pragma unroll
                for (int nj = 0; nj < 8; nj++) {
                    const int col = nj * 8 + tg * 2;
                    *(float2*)(Stg + rg * 68 + col) = make_float2(
                        tf32r(fexp(acc[mi][nj][half * 2    ] + e) * invs),
                        tf32r(fexp(acc[mi][nj][half * 2 + 1] + e) * invs));
                }
            }
        }
#pragma unroll
        for (int it = 0; it < 4; it++) {
            int f = it * 256 + t;
            int r = f >> 4, dq = f & 15;
            float4 v = *(const float4*)(g_S + ((size_t)bh * M_ + s * 64 + r) * DK_ + dq * 4);
            v.x = tf32r(v.x); v.y = tf32r(v.y);
            v.z = tf32r(v.z); v.w = tf32r(v.w);
            *(float4*)(Ss + r * 72 + dq * 4) = v;
        }
        if (t < 64) Kss[t] = g_Ksum[(size_t)bh * M_ + s * 64 + t];
        __syncthreads();
        {
            const int r = t >> 2, fg = (t & 3) * 16;
#pragma unroll
            for (int i = 0; i < 16; i++)
                dpart = fmaf(Stg[r * 68 + fg + i], Kss[fg + i], dpart);
        }
#pragma unroll
        for (int ks = 0; ks < 8; ks++) {
            const int k0 = ks * 8;
            uint32_t ah[2][4], bhf[2][2];
#pragma unroll
            for (int mi = 0; mi < 2; mi++) {
                const int m0 = wm * 32 + mi * 16;
                ah[mi][0] = __float_as_uint(Stg[(m0 + g    ) * 68 + k0 + tg    ]);
                ah[mi][1] = __float_as_uint(Stg[(m0 + g + 8) * 68 + k0 + tg    ]);
                ah[mi][2] = __float_as_uint(Stg[(m0 + g    ) * 68 + k0 + tg + 4]);
                ah[mi][3] = __float_as_uint(Stg[(m0 + g + 8) * 68 + k0 + tg + 4]);
            }
#pragma unroll
            for (int nj = 0; nj < 2; nj++) {
                const int n0d = wn * 16 + nj * 8;
                bhf[nj][0] = __float_as_uint(Ss[(k0 + tg    ) * 72 + n0d + g]);
                bhf[nj][1] = __float_as_uint(Ss[(k0 + tg + 4) * 72 + n0d + g]);
            }
#pragma unroll
            for (int mi = 0; mi < 2; mi++)
#pragma unroll
                for (int nj = 0; nj < 2; nj++) mma_tf32(accC[mi][nj], ah[mi], bhf[nj]);
        }
    }
    dpart += __shfl_xor_sync(0xffffffffu, dpart, 1);
    dpart += __shfl_xor_sync(0xffffffffu, dpart, 2);
    if ((t & 3) == 0) s_den[t >> 2] = dpart;
    __syncthreads();

#pragma unroll
    for (int mi = 0; mi < 2; mi++) {
        const int r0 = wm * 32 + mi * 16 + g;
#pragma unroll
        for (int nj = 0; nj < 2; nj++) {
            const int dk = wn * 16 + nj * 8 + tg * 2;
#pragma unroll
            for (int half = 0; half < 2; half++) {
                const int r = r0 + half * 8;
                const float vv = g_valid[bI * N_ + n0 + r];
                const float dn = vv / (s_den[r] + 1e-6f);
                *(float2*)(g_ctx + ((size_t)bI * N_ + n0 + r) * D_ + h * DK_ + dk) =
                    make_float2(accC[mi][nj][half * 2] * dn,
                                accC[mi][nj][half * 2 + 1] * dn);
            }
        }
    }
}

// ========================= launch ========================================
extern "C" void kernel_launch(void* const* d_in, const int* in_sizes, int n_in,
                              void* d_out, int out_size) {
    (void)in_sizes; (void)n_in; (void)out_size;
    const float* x     = (const float*)d_in[0];
    const float* Wqkv  = (const float*)d_in[1];
    const float* bqkv  = (const float*)d_in[2];
    const float* Wout  = (const float*)d_in[3];
    const float* bout  = (const float*)d_in[4];
    const float* omega = (const float*)d_in[5];
    const void*  mask  = d_in[6];
    float* out = (float*)d_out;

    k_mask<<<1, 256>>>(mask);
    k_omsplit<<<512, 256>>>(omega);
    k_gemm_mma<<<dim3(24, 128), 256>>>(x, Wqkv, bqkv, nullptr, 0);
    k_phik_spart<<<dim3(BH_, CH_), 256>>>();
    {
        const int tot = BH_ * M_ * (DK_ + 1);
        k_sreduce<<<(tot + 255) / 256, 256>>>();
    }
    k_phiq_ctx<<<dim3(BH_, N_ / 64), 256>>>();
    k_gemm_mma<<<dim3(8, 128), 256>>>(x, Wout, bout, out, 1);
}